// round 2
// baseline (speedup 1.0000x reference)
#include <cuda_runtime.h>

#define Hd   1024
#define BATCH 128
#define TSEQ  128
#define DIN    64
#define GRID  128
#define NTHR  128

typedef unsigned long long ull;

// ---------------- persistent state (device globals; no allocation) ----------
__device__ float g_h1[2][BATCH * Hd];
__device__ float g_c1[BATCH * Hd];
__device__ float g_h2[2][BATCH * Hd];
__device__ float g_c2[BATCH * Hd];
__device__ float g_out[BATCH * DIN];
__device__ unsigned g_bar_cnt;               // always returns to 0 each barrier
__device__ volatile unsigned g_bar_gen;      // monotonically increases across replays (compared by equality)

// ---------------- packed f32x2 FMA (SASS FFMA2; PTX-only encoding) ----------
#define FMA2(acc, a, w) asm("fma.rn.f32x2 %0, %1, %2, %0;" : "+l"(acc) : "l"(a), "l"(w))

__device__ __forceinline__ float2 unpack2(ull v) {
    float2 r;
    asm("mov.b64 {%0,%1}, %2;" : "=f"(r.x), "=f"(r.y) : "l"(v));
    return r;
}

__device__ __forceinline__ float sigm(float v) {
    return 1.0f / (1.0f + expf(-v));
}

// ---------------- grid-wide barrier (all 128 blocks co-resident) ------------
__device__ __forceinline__ void grid_bar() {
    __syncthreads();
    if (threadIdx.x == 0) {
        unsigned gen = g_bar_gen;
        __threadfence();                       // release: my writes visible
        unsigned t = atomicAdd(&g_bar_cnt, 1u);
        if (t == GRID - 1) {
            atomicExch(&g_bar_cnt, 0u);        // reset for next barrier
            __threadfence();
            g_bar_gen = gen + 1;               // release the others
        } else {
            while (g_bar_gen == gen) { __nanosleep(64); }
        }
        __threadfence();                       // acquire
    }
    __syncthreads();
}

// ---------------- GEMM accumulation over one A/W source ---------------------
// Block tile: 64 batches x 16 cols x 4 gates. Thread: 8 batches x 1 col x 4 gates.
// acc[bp][g] is an f32x2 pair over batches (2bp, 2bp+1) of this thread's bgroup.
// A is staged k-major in smem; W is staged lane-duplicated (w,w) so the inner
// loop is 4x LDS.128 + 16x FFMA2 per k (fma-pipe bound).
__device__ __forceinline__ void accum_ks(
    const float* __restrict__ A, int lda,      // A[b][k] = A[b*lda + k], b local 0..63
    const float* __restrict__ W, int ldw,      // W[r][k] = W[r*ldw + k], r = g*Hd + n
    int K, int n0, ull acc[4][4],
    float (*sA)[64], float2 (*sW)[16][4])
{
    const int tid  = threadIdx.x;
    const int arow = tid >> 1;                 // 0..63 (batch row / W logical row)
    const int kh   = (tid & 1) << 4;           // 0 or 16 (k half of chunk)
    const int colw = arow & 15;                // W logical row -> (col, gate)
    const int gw   = arow >> 2 >> 2;           // arow >> 4
    const int bg   = tid >> 4;                 // 0..7  (8 batches each)
    const int col  = tid & 15;                 // 0..15

    const float* ap = A + arow * lda + kh;
    const float* wp = W + (gw * Hd + n0 + colw) * ldw + kh;

    float4 ar[4], wr[4];
#pragma unroll
    for (int j = 0; j < 4; j++) {
        ar[j] = __ldcg((const float4*)(ap + j * 4));   // h/x/out: L1-bypass (coherence)
        wr[j] = __ldg ((const float4*)(wp + j * 4));   // weights: immutable
    }

    const int nch = K >> 5;
    for (int c = 0; c < nch; c++) {
        __syncthreads();                       // previous compute done -> smem free
#pragma unroll
        for (int j = 0; j < 4; j++) {
            sA[kh + j * 4 + 0][arow] = ar[j].x;
            sA[kh + j * 4 + 1][arow] = ar[j].y;
            sA[kh + j * 4 + 2][arow] = ar[j].z;
            sA[kh + j * 4 + 3][arow] = ar[j].w;
            sW[kh + j * 4 + 0][colw][gw] = make_float2(wr[j].x, wr[j].x);
            sW[kh + j * 4 + 1][colw][gw] = make_float2(wr[j].y, wr[j].y);
            sW[kh + j * 4 + 2][colw][gw] = make_float2(wr[j].z, wr[j].z);
            sW[kh + j * 4 + 3][colw][gw] = make_float2(wr[j].w, wr[j].w);
        }
        if (c + 1 < nch) {                     // prefetch next chunk (overlaps compute)
            const float* ap2 = ap + (c + 1) * 32;
            const float* wp2 = wp + (c + 1) * 32;
#pragma unroll
            for (int j = 0; j < 4; j++) {
                ar[j] = __ldcg((const float4*)(ap2 + j * 4));
                wr[j] = __ldg ((const float4*)(wp2 + j * 4));
            }
        }
        __syncthreads();                       // smem tile ready

#pragma unroll 16
        for (int k = 0; k < 32; k++) {
            ulonglong2 a01 = *(const ulonglong2*)&sA[k][bg * 8];
            ulonglong2 a23 = *(const ulonglong2*)&sA[k][bg * 8 + 4];
            ulonglong2 w01 = *(const ulonglong2*)&sW[k][col][0];
            ulonglong2 w23 = *(const ulonglong2*)&sW[k][col][2];
            ull Av[4] = { a01.x, a01.y, a23.x, a23.y };
            ull Wv[4] = { w01.x, w01.y, w23.x, w23.y };
#pragma unroll
            for (int bp = 0; bp < 4; bp++) {
#pragma unroll
                for (int g = 0; g < 4; g++) {
                    FMA2(acc[bp][g], Av[bp], Wv[g]);
                }
            }
        }
    }
}

// ---------------- one LSTM cell step for this block's tile ------------------
__device__ __noinline__ void lstm_layer(
    const float* Ax, int ldax, int Kx,         // input part (already offset by b0)
    const float* Ahr,                          // recurrent h (already offset by b0), ld = Hd, K = Hd
    const float* Wih, int ldwih,
    const float* Whh,
    const float* __restrict__ bih, const float* __restrict__ bhh,
    float* cbuf, float* hout,
    int b0, int n0,
    float (*sA)[64], float2 (*sW)[16][4])
{
    ull acc[4][4];
#pragma unroll
    for (int i = 0; i < 4; i++)
#pragma unroll
        for (int j = 0; j < 4; j++) acc[i][j] = 0ULL;   // (0.f, 0.f)

    accum_ks(Ax,  ldax, Wih, ldwih, Kx, n0, acc, sA, sW);
    accum_ks(Ahr, Hd,   Whh, Hd,   Hd, n0, acc, sA, sW);

    const int tid = threadIdx.x;
    const int bg  = tid >> 4;
    const int col = tid & 15;
    const int n   = n0 + col;

    const float bi = bih[n]          + bhh[n];
    const float bf = bih[Hd + n]     + bhh[Hd + n];
    const float bg_ = bih[2 * Hd + n] + bhh[2 * Hd + n];
    const float bo = bih[3 * Hd + n] + bhh[3 * Hd + n];

#pragma unroll
    for (int bp = 0; bp < 4; bp++) {
        float2 vi = unpack2(acc[bp][0]);
        float2 vf = unpack2(acc[bp][1]);
        float2 vg = unpack2(acc[bp][2]);
        float2 vo = unpack2(acc[bp][3]);
#pragma unroll
        for (int lane = 0; lane < 2; lane++) {
            const int b = b0 + bg * 8 + bp * 2 + lane;
            const float iv = (lane ? vi.y : vi.x) + bi;
            const float fv = (lane ? vf.y : vf.x) + bf;
            const float gv = (lane ? vg.y : vg.x) + bg_;
            const float ov = (lane ? vo.y : vo.x) + bo;
            const int idx = b * Hd + n;
            const float cn = sigm(fv) * cbuf[idx] + sigm(iv) * tanhf(gv);
            cbuf[idx] = cn;                     // block-private: plain st ok
            hout[idx] = sigm(ov) * tanhf(cn);
        }
    }
}

// ---------------- small output linear: out[b][d] = h[b]·W[d] + bias[d] ------
__device__ __noinline__ void linear64(
    const float* hsrc, const float* __restrict__ W,
    const float* __restrict__ bias, float* outp, int blk, int tid)
{
    const int d = tid >> 1, half = tid & 1;
    const float* hb = hsrc + blk * Hd + half * 512;
    const float* wd = W    + d   * Hd + half * 512;
    float s = 0.f;
#pragma unroll 8
    for (int k = 0; k < 512; k += 4) {
        float4 hv = __ldcg((const float4*)(hb + k));
        float4 wv = __ldg ((const float4*)(wd + k));
        s += hv.x * wv.x + hv.y * wv.y + hv.z * wv.z + hv.w * wv.w;
    }
    s += __shfl_xor_sync(0xffffffffu, s, 1);
    if (!half) outp[blk * DIN + d] = s + bias[d];
}

// ---------------- persistent fused kernel -----------------------------------
__global__ void __launch_bounds__(NTHR, 1) lstm_fused(
    const float* __restrict__ x,
    const float* __restrict__ Wih1, const float* __restrict__ Whh1,
    const float* __restrict__ bih1, const float* __restrict__ bhh1,
    const float* __restrict__ Wih2, const float* __restrict__ Whh2,
    const float* __restrict__ bih2, const float* __restrict__ bhh2,
    const float* __restrict__ Wlin, const float* __restrict__ blin,
    const float* __restrict__ Whio, const float* __restrict__ bhio,
    const int*  __restrict__ futp,
    float* __restrict__ out)
{
    __shared__ __align__(16) float  sA[32][64];       // A tile, k-major (8 KB)
    __shared__ __align__(16) float2 sW[32][16][4];    // W tile, lane-duplicated (16 KB)

    const int tid = threadIdx.x;
    const int blk = blockIdx.x;
    const int b0  = (blk >> 6) * 64;   // batch half: 0 or 64
    const int n0  = (blk & 63) * 16;   // 16 H-columns

    // zero persistent state for this block's tile (fresh every launch)
    for (int i = tid; i < 64 * 16; i += NTHR) {
        const int bb = i >> 4, nn = i & 15;
        const int idx = (b0 + bb) * Hd + n0 + nn;
        g_h1[0][idx] = 0.f; g_c1[idx] = 0.f;
        g_h2[0][idx] = 0.f; g_c2[idx] = 0.f;
    }
    const int fut = *futp;
    grid_bar();

    int p = 0;  // read buffer parity; write buffer = 1-p
    for (int t = 0; t < TSEQ; t++) {
        lstm_layer(x + b0 * (TSEQ * DIN) + t * DIN, TSEQ * DIN, DIN,
                   g_h1[p] + b0 * Hd, Wih1, DIN, Whh1, bih1, bhh1,
                   g_c1, g_h1[1 - p], b0, n0, sA, sW);
        grid_bar();
        lstm_layer(g_h1[1 - p] + b0 * Hd, Hd, Hd,
                   g_h2[p] + b0 * Hd, Wih2, Hd, Whh2, bih2, bhh2,
                   g_c2, g_h2[1 - p], b0, n0, sA, sW);
        grid_bar();
        p ^= 1;
    }

    // output = h2 @ Wlin^T + blin (input to future step 0; final answer if fut==0)
    linear64(g_h2[p], Wlin, blin, g_out, blk, tid);
    grid_bar();

    for (int f = 0; f < fut; f++) {
        lstm_layer(g_out + b0 * DIN, DIN, DIN,
                   g_h1[p] + b0 * Hd, Wih1, DIN, Whh1, bih1, bhh1,
                   g_c1, g_h1[1 - p], b0, n0, sA, sW);
        grid_bar();
        lstm_layer(g_h1[1 - p] + b0 * Hd, Hd, Hd,
                   g_h2[p] + b0 * Hd, Wih2, Hd, Whh2, bih2, bhh2,
                   g_c2, g_h2[1 - p], b0, n0, sA, sW);
        grid_bar();
        p ^= 1;
        linear64(g_h2[p], Whio, bhio, g_out, blk, tid);
        grid_bar();
    }

    // write final output [B, 1, DIN]; block blk owns batch row blk
    for (int d = tid; d < DIN; d += NTHR)
        out[blk * DIN + d] = g_out[blk * DIN + d];
}

extern "C" void kernel_launch(void* const* d_in, const int* in_sizes, int n_in,
                              void* d_out, int out_size)
{
    const float* x    = (const float*)d_in[0];
    const float* Wih1 = (const float*)d_in[1];
    const float* Whh1 = (const float*)d_in[2];
    const float* bih1 = (const float*)d_in[3];
    const float* bhh1 = (const float*)d_in[4];
    const float* Wih2 = (const float*)d_in[5];
    const float* Whh2 = (const float*)d_in[6];
    const float* bih2 = (const float*)d_in[7];
    const float* bhh2 = (const float*)d_in[8];
    const float* Wlin = (const float*)d_in[9];
    const float* blin = (const float*)d_in[10];
    const float* Whio = (const float*)d_in[11];
    const float* bhio = (const float*)d_in[12];
    const int*   futp = (const int*)d_in[13];

    lstm_fused<<<GRID, NTHR>>>(x, Wih1, Whh1, bih1, bhh1,
                               Wih2, Whh2, bih2, bhh2,
                               Wlin, blin, Whio, bhio,
                               futp, (float*)d_out);
}

// round 3
// speedup vs baseline: 1.6559x; 1.6559x over previous
#include <cuda_runtime.h>

#define Hd   1024
#define BATCH 128
#define TSEQ  128
#define DIN    64
#define GRID  128
#define NTHR  128

typedef unsigned long long ull;

// ---------------- persistent state (device globals; no allocation) ----------
__device__ float g_h1[2][BATCH * Hd];
__device__ float g_c1[BATCH * Hd];
__device__ float g_h2[2][BATCH * Hd];
__device__ float g_c2[BATCH * Hd];
__device__ float g_out[BATCH * DIN];
__device__ unsigned g_bar_cnt;               // always returns to 0 each barrier
__device__ volatile unsigned g_bar_gen;      // monotonically increases across replays (compared by equality)

// ---------------- packed f32x2 FMA (SASS FFMA2; PTX-only encoding) ----------
#define FMA2(acc, a, w) asm("fma.rn.f32x2 %0, %1, %2, %0;" : "+l"(acc) : "l"(a), "l"(w))

__device__ __forceinline__ float2 unpack2(ull v) {
    float2 r;
    asm("mov.b64 {%0,%1}, %2;" : "=f"(r.x), "=f"(r.y) : "l"(v));
    return r;
}

__device__ __forceinline__ float sigm(float v) {
    return 1.0f / (1.0f + expf(-v));
}

// ---------------- grid-wide barrier (all 128 blocks co-resident) ------------
__device__ __forceinline__ void grid_bar() {
    __syncthreads();
    if (threadIdx.x == 0) {
        unsigned gen = g_bar_gen;
        __threadfence();                       // release: my writes visible
        unsigned t = atomicAdd(&g_bar_cnt, 1u);
        if (t == GRID - 1) {
            atomicExch(&g_bar_cnt, 0u);        // reset for next barrier
            __threadfence();
            g_bar_gen = gen + 1;               // release the others
        } else {
            while (g_bar_gen == gen) { __nanosleep(64); }
        }
        __threadfence();                       // acquire
    }
    __syncthreads();
}

// ---------------- GEMM accumulation over one A/W source ---------------------
// Block tile: 64 batches x 16 cols x 4 gates. Thread: 8 batches x 1 col x 4 gates.
// acc[bp][g] is an f32x2 pair over batches (2bp, 2bp+1) of this thread's bgroup.
// A is staged k-major in smem; W is staged lane-duplicated (w,w) so the inner
// loop is 4x LDS.128 + 16x FFMA2 per k (fma-pipe bound).
__device__ __forceinline__ void accum_ks(
    const float* __restrict__ A, int lda,      // A[b][k] = A[b*lda + k], b local 0..63
    const float* __restrict__ W, int ldw,      // W[r][k] = W[r*ldw + k], r = g*Hd + n
    int K, int n0, ull acc[4][4],
    float (*sA)[64], float2 (*sW)[16][4])
{
    const int tid  = threadIdx.x;
    const int arow = tid >> 1;                 // 0..63 (batch row / W logical row)
    const int kh   = (tid & 1) << 4;           // 0 or 16 (k half of chunk)
    const int colw = arow & 15;                // W logical row -> (col, gate)
    const int gw   = arow >> 2 >> 2;           // arow >> 4
    const int bg   = tid >> 4;                 // 0..7  (8 batches each)
    const int col  = tid & 15;                 // 0..15

    const float* ap = A + arow * lda + kh;
    const float* wp = W + (gw * Hd + n0 + colw) * ldw + kh;

    float4 ar[4], wr[4];
#pragma unroll
    for (int j = 0; j < 4; j++) {
        ar[j] = __ldcg((const float4*)(ap + j * 4));   // h/x/out: L1-bypass (coherence)
        wr[j] = __ldg ((const float4*)(wp + j * 4));   // weights: immutable
    }

    const int nch = K >> 5;
    for (int c = 0; c < nch; c++) {
        __syncthreads();                       // previous compute done -> smem free
#pragma unroll
        for (int j = 0; j < 4; j++) {
            sA[kh + j * 4 + 0][arow] = ar[j].x;
            sA[kh + j * 4 + 1][arow] = ar[j].y;
            sA[kh + j * 4 + 2][arow] = ar[j].z;
            sA[kh + j * 4 + 3][arow] = ar[j].w;
            sW[kh + j * 4 + 0][colw][gw] = make_float2(wr[j].x, wr[j].x);
            sW[kh + j * 4 + 1][colw][gw] = make_float2(wr[j].y, wr[j].y);
            sW[kh + j * 4 + 2][colw][gw] = make_float2(wr[j].z, wr[j].z);
            sW[kh + j * 4 + 3][colw][gw] = make_float2(wr[j].w, wr[j].w);
        }
        if (c + 1 < nch) {                     // prefetch next chunk (overlaps compute)
            const float* ap2 = ap + (c + 1) * 32;
            const float* wp2 = wp + (c + 1) * 32;
#pragma unroll
            for (int j = 0; j < 4; j++) {
                ar[j] = __ldcg((const float4*)(ap2 + j * 4));
                wr[j] = __ldg ((const float4*)(wp2 + j * 4));
            }
        }
        __syncthreads();                       // smem tile ready

#pragma unroll 16
        for (int k = 0; k < 32; k++) {
            ulonglong2 a01 = *(const ulonglong2*)&sA[k][bg * 8];
            ulonglong2 a23 = *(const ulonglong2*)&sA[k][bg * 8 + 4];
            ulonglong2 w01 = *(const ulonglong2*)&sW[k][col][0];
            ulonglong2 w23 = *(const ulonglong2*)&sW[k][col][2];
            ull Av[4] = { a01.x, a01.y, a23.x, a23.y };
            ull Wv[4] = { w01.x, w01.y, w23.x, w23.y };
#pragma unroll
            for (int bp = 0; bp < 4; bp++) {
#pragma unroll
                for (int g = 0; g < 4; g++) {
                    FMA2(acc[bp][g], Av[bp], Wv[g]);
                }
            }
        }
    }
}

// ---------------- one LSTM cell step for this block's tile ------------------
__device__ __noinline__ void lstm_layer(
    const float* Ax, int ldax, int Kx,         // input part (already offset by b0)
    const float* Ahr,                          // recurrent h (already offset by b0), ld = Hd, K = Hd
    const float* Wih, int ldwih,
    const float* Whh,
    const float* __restrict__ bih, const float* __restrict__ bhh,
    float* cbuf, float* hout,
    int b0, int n0,
    float (*sA)[64], float2 (*sW)[16][4])
{
    ull acc[4][4];
#pragma unroll
    for (int i = 0; i < 4; i++)
#pragma unroll
        for (int j = 0; j < 4; j++) acc[i][j] = 0ULL;   // (0.f, 0.f)

    accum_ks(Ax,  ldax, Wih, ldwih, Kx, n0, acc, sA, sW);
    accum_ks(Ahr, Hd,   Whh, Hd,   Hd, n0, acc, sA, sW);

    const int tid = threadIdx.x;
    const int bg  = tid >> 4;
    const int col = tid & 15;
    const int n   = n0 + col;

    const float bi = bih[n]          + bhh[n];
    const float bf = bih[Hd + n]     + bhh[Hd + n];
    const float bg_ = bih[2 * Hd + n] + bhh[2 * Hd + n];
    const float bo = bih[3 * Hd + n] + bhh[3 * Hd + n];

#pragma unroll
    for (int bp = 0; bp < 4; bp++) {
        float2 vi = unpack2(acc[bp][0]);
        float2 vf = unpack2(acc[bp][1]);
        float2 vg = unpack2(acc[bp][2]);
        float2 vo = unpack2(acc[bp][3]);
#pragma unroll
        for (int lane = 0; lane < 2; lane++) {
            const int b = b0 + bg * 8 + bp * 2 + lane;
            const float iv = (lane ? vi.y : vi.x) + bi;
            const float fv = (lane ? vf.y : vf.x) + bf;
            const float gv = (lane ? vg.y : vg.x) + bg_;
            const float ov = (lane ? vo.y : vo.x) + bo;
            const int idx = b * Hd + n;
            const float cn = sigm(fv) * cbuf[idx] + sigm(iv) * tanhf(gv);
            cbuf[idx] = cn;                     // block-private: plain st ok
            hout[idx] = sigm(ov) * tanhf(cn);
        }
    }
}

// ---------------- small output linear: out[b][d] = h[b]·W[d] + bias[d] ------
__device__ __noinline__ void linear64(
    const float* hsrc, const float* __restrict__ W,
    const float* __restrict__ bias, float* outp, int blk, int tid)
{
    const int d = tid >> 1, half = tid & 1;
    const float* hb = hsrc + blk * Hd + half * 512;
    const float* wd = W    + d   * Hd + half * 512;
    float s = 0.f;
#pragma unroll 8
    for (int k = 0; k < 512; k += 4) {
        float4 hv = __ldcg((const float4*)(hb + k));
        float4 wv = __ldg ((const float4*)(wd + k));
        s += hv.x * wv.x + hv.y * wv.y + hv.z * wv.z + hv.w * wv.w;
    }
    s += __shfl_xor_sync(0xffffffffu, s, 1);
    if (!half) outp[blk * DIN + d] = s + bias[d];
}

// ---------------- persistent fused kernel -----------------------------------
__global__ void __launch_bounds__(NTHR, 1) lstm_fused(
    const float* __restrict__ x,
    const float* __restrict__ Wih1, const float* __restrict__ Whh1,
    const float* __restrict__ bih1, const float* __restrict__ bhh1,
    const float* __restrict__ Wih2, const float* __restrict__ Whh2,
    const float* __restrict__ bih2, const float* __restrict__ bhh2,
    const float* __restrict__ Wlin, const float* __restrict__ blin,
    const float* __restrict__ Whio, const float* __restrict__ bhio,
    const int*  __restrict__ futp,
    float* __restrict__ out)
{
    __shared__ __align__(16) float  sA[32][64];       // A tile, k-major (8 KB)
    __shared__ __align__(16) float2 sW[32][16][4];    // W tile, lane-duplicated (16 KB)

    const int tid = threadIdx.x;
    const int blk = blockIdx.x;
    const int b0  = (blk >> 6) * 64;   // batch half: 0 or 64
    const int n0  = (blk & 63) * 16;   // 16 H-columns

    // zero persistent state for this block's tile (fresh every launch)
    for (int i = tid; i < 64 * 16; i += NTHR) {
        const int bb = i >> 4, nn = i & 15;
        const int idx = (b0 + bb) * Hd + n0 + nn;
        g_h1[0][idx] = 0.f; g_c1[idx] = 0.f;
        g_h2[0][idx] = 0.f; g_c2[idx] = 0.f;
    }
    const int fut = *futp;
    grid_bar();

    int p = 0;  // read buffer parity; write buffer = 1-p
    for (int t = 0; t < TSEQ; t++) {
        lstm_layer(x + b0 * (TSEQ * DIN) + t * DIN, TSEQ * DIN, DIN,
                   g_h1[p] + b0 * Hd, Wih1, DIN, Whh1, bih1, bhh1,
                   g_c1, g_h1[1 - p], b0, n0, sA, sW);
        grid_bar();
        lstm_layer(g_h1[1 - p] + b0 * Hd, Hd, Hd,
                   g_h2[p] + b0 * Hd, Wih2, Hd, Whh2, bih2, bhh2,
                   g_c2, g_h2[1 - p], b0, n0, sA, sW);
        grid_bar();
        p ^= 1;
    }

    // output = h2 @ Wlin^T + blin (input to future step 0; final answer if fut==0)
    linear64(g_h2[p], Wlin, blin, g_out, blk, tid);
    grid_bar();

    for (int f = 0; f < fut; f++) {
        lstm_layer(g_out + b0 * DIN, DIN, DIN,
                   g_h1[p] + b0 * Hd, Wih1, DIN, Whh1, bih1, bhh1,
                   g_c1, g_h1[1 - p], b0, n0, sA, sW);
        grid_bar();
        lstm_layer(g_h1[1 - p] + b0 * Hd, Hd, Hd,
                   g_h2[p] + b0 * Hd, Wih2, Hd, Whh2, bih2, bhh2,
                   g_c2, g_h2[1 - p], b0, n0, sA, sW);
        grid_bar();
        p ^= 1;
        linear64(g_h2[p], Whio, bhio, g_out, blk, tid);
        grid_bar();
    }

    // write final output [B, 1, DIN]; block blk owns batch row blk
    for (int d = tid; d < DIN; d += NTHR)
        out[blk * DIN + d] = g_out[blk * DIN + d];
}

extern "C" void kernel_launch(void* const* d_in, const int* in_sizes, int n_in,
                              void* d_out, int out_size)
{
    const float* x    = (const float*)d_in[0];
    const float* Wih1 = (const float*)d_in[1];
    const float* Whh1 = (const float*)d_in[2];
    const float* bih1 = (const float*)d_in[3];
    const float* bhh1 = (const float*)d_in[4];
    const float* Wih2 = (const float*)d_in[5];
    const float* Whh2 = (const float*)d_in[6];
    const float* bih2 = (const float*)d_in[7];
    const float* bhh2 = (const float*)d_in[8];
    const float* Wlin = (const float*)d_in[9];
    const float* blin = (const float*)d_in[10];
    const float* Whio = (const float*)d_in[11];
    const float* bhio = (const float*)d_in[12];
    const int*   futp = (const int*)d_in[13];

    lstm_fused<<<GRID, NTHR>>>(x, Wih1, Whh1, bih1, bhh1,
                               Wih2, Whh2, bih2, bhh2,
                               Wlin, blin, Whio, bhio,
                               futp, (float*)d_out);
}

// round 6
// speedup vs baseline: 6.3649x; 3.8437x over previous
#include <cuda_runtime.h>
#include <cuda_bf16.h>
#include <cstdint>

#define Hd    1024
#define TSEQ  128
#define DIN   64
#define GRID  128
#define NTHR  256

#define NSTG      4
#define SLOT_SZ   40960                    // Ah 16K | Al 16K | Wh 4K | Wl 4K
#define OFF_D     (NSTG * SLOT_SZ)        // 163840
#define D_PITCH   36
#define DYN_SMEM  (OFF_D + 128 * D_PITCH * 4)   // 182272

// ---------------- device globals (packed layouts; no allocation) ------------
__device__ __align__(1024) __nv_bfloat16 gPWih1[128][2][2048];       // [c][pl][32*64]
__device__ __align__(1024) __nv_bfloat16 gPWhh1[128][16][2][2048];
__device__ __align__(1024) __nv_bfloat16 gPWih2[128][16][2][2048];
__device__ __align__(1024) __nv_bfloat16 gPWhh2[128][16][2][2048];
__device__ __align__(1024) __nv_bfloat16 gPX[TSEQ][2][8192];         // [t][pl][64k*128b]
__device__ __align__(1024) __nv_bfloat16 gH1T[2][2][131072];         // [par][pl][1024k*128b]
__device__ __align__(1024) __nv_bfloat16 gH2T[2][2][131072];
__device__ __align__(1024) __nv_bfloat16 gOutT[2][8192];             // [pl][64k*128b]
__device__ float gH2f[128 * Hd];
__device__ float gOut[128 * DIN];
__device__ float gBias[2][4096];
__device__ unsigned g_bar_cnt;
__device__ volatile unsigned g_bar_gen;

// ---------------- PTX helpers ------------------------------------------------
__device__ __forceinline__ uint32_t smem_u32(const void* p) {
    uint32_t a;
    asm("{ .reg .u64 t; cvta.to.shared.u64 t, %1; cvt.u32.u64 %0, t; }" : "=r"(a) : "l"(p));
    return a;
}
#define MBAR_INIT(a, c) \
    asm volatile("mbarrier.init.shared.b64 [%0], %1;" :: "r"(a), "r"((uint32_t)(c)) : "memory")
#define MBAR_ARRIVE(a) \
    asm volatile("mbarrier.arrive.shared.b64 _, [%0];" :: "r"(a) : "memory")
#define MBAR_EXPECT_TX(a, n) \
    asm volatile("mbarrier.arrive.expect_tx.shared.b64 _, [%0], %1;" :: "r"(a), "r"((uint32_t)(n)) : "memory")
#define MBAR_WAIT(a, ph) do { \
    uint32_t _m = (a), _p = (uint32_t)(ph), _d; \
    asm volatile("{\n\t.reg .pred p;\n\t" \
        "mbarrier.try_wait.parity.acquire.cta.shared::cta.b64 p, [%1], %2;\n\t" \
        "selp.b32 %0, 1, 0, p;\n\t}" : "=r"(_d) : "r"(_m), "r"(_p) : "memory"); \
    if (!_d) { \
        asm volatile("{\n\t.reg .pred P1;\n\t" \
            "WL_%=:\n\t" \
            "mbarrier.try_wait.parity.acquire.cta.shared::cta.b64 P1, [%0], %1, 0x989680;\n\t" \
            "@P1 bra.uni WD_%=;\n\tbra.uni WL_%=;\n\tWD_%=:\n\t}" \
            :: "r"(_m), "r"(_p) : "memory"); \
    } } while (0)
#define BULK_G2S(dst, src, sz, mb) \
    asm volatile("cp.async.bulk.shared::cta.global.mbarrier::complete_tx::bytes [%0], [%1], %2, [%3];" \
                 :: "r"(dst), "l"(src), "r"((uint32_t)(sz)), "r"(mb) : "memory")
#define LDSM4(r, a) \
    asm volatile("ldmatrix.sync.aligned.m8n8.x4.shared.b16 {%0,%1,%2,%3},[%4];" \
        : "=r"((r)[0]), "=r"((r)[1]), "=r"((r)[2]), "=r"((r)[3]) : "r"(a))
#define LDSM4T(r, a) \
    asm volatile("ldmatrix.sync.aligned.m8n8.x4.trans.shared.b16 {%0,%1,%2,%3},[%4];" \
        : "=r"((r)[0]), "=r"((r)[1]), "=r"((r)[2]), "=r"((r)[3]) : "r"(a))

__device__ __forceinline__ void mma16816(float* c, const uint32_t* a, uint32_t b0, uint32_t b1) {
    asm volatile("mma.sync.aligned.m16n8k16.row.col.f32.bf16.bf16.f32 "
                 "{%0,%1,%2,%3},{%4,%5,%6,%7},{%8,%9},{%0,%1,%2,%3};"
                 : "+f"(c[0]), "+f"(c[1]), "+f"(c[2]), "+f"(c[3])
                 : "r"(a[0]), "r"(a[1]), "r"(a[2]), "r"(a[3]), "r"(b0), "r"(b1));
}
__device__ __forceinline__ uint32_t sw128(uint32_t o) { return o ^ ((o >> 3) & 0x70); }
__device__ __forceinline__ uint32_t sw256(uint32_t o) { return o ^ ((o >> 4) & 0x70); }
__device__ __forceinline__ float sigm(float v) { return 1.0f / (1.0f + __expf(-v)); }

// ---------------- grid-wide barrier -----------------------------------------
__device__ __forceinline__ void grid_bar() {
    __syncthreads();
    if (threadIdx.x == 0) {
        unsigned gen = g_bar_gen;
        __threadfence();
        unsigned t = atomicAdd(&g_bar_cnt, 1u);
        if (t == GRID - 1) {
            atomicExch(&g_bar_cnt, 0u);
            __threadfence();
            g_bar_gen = gen + 1;
        } else {
            while (g_bar_gen == gen) { __nanosleep(64); }
        }
        __threadfence();
    }
    __syncthreads();
}

// ---------------- pipeline ---------------------------------------------------
struct Cur { unsigned pi, ci; int pph, cph; };
__shared__ __align__(8) uint64_t sFull[NSTG], sEmpty[NSTG];
__shared__ float sBias[64];

__device__ __forceinline__ void produce(Cur& C, uint32_t smb, char* const* src) {
    const int s = C.pi & (NSTG - 1);
    if (threadIdx.x == 0) {
        MBAR_WAIT(smem_u32(&sEmpty[s]), C.pph);
        const uint32_t mf = smem_u32(&sFull[s]);
        MBAR_EXPECT_TX(mf, SLOT_SZ);
        const uint32_t d = smb + s * SLOT_SZ;
        BULK_G2S(d,          src[0], 16384, mf);
        BULK_G2S(d + 16384,  src[1], 16384, mf);
        BULK_G2S(d + 32768,  src[2], 8192,  mf);
    }
    C.pi++; if (!(C.pi & (NSTG - 1))) C.pph ^= 1;
}

__device__ __forceinline__ void consume(Cur& C, uint32_t smb, float acc[4][4]) {
    const int s = C.ci & (NSTG - 1);
    MBAR_WAIT(smem_u32(&sFull[s]), C.cph);
    const uint32_t bA = smb + s * SLOT_SZ;
    const uint32_t bW = bA + 32768;
    const int lane = threadIdx.x & 31, w = threadIdx.x >> 5;
    const int kpart = ((lane >> 4) & 1) * 8 + (lane & 7);          // A: k within step
    const int bsegA = (w << 5) + ((lane >> 3) & 1) * 16;           // A: b segment bytes
    const int nsub  = ((lane >> 4) & 1) * 8 + (lane & 7);          // W: n within pair-tile
    const int khB   = ((lane >> 3) & 1) * 16;                      // W: k half bytes
#pragma unroll
    for (int ks = 0; ks < 4; ks++) {
        uint32_t ah[4], al[4], wh0[4], wh1[4], wl0[4], wl1[4];
        const uint32_t oA = sw256((uint32_t)((ks * 16 + kpart) * 256 + bsegA));
        LDSM4T(ah, bA + oA);
        LDSM4T(al, bA + 16384 + oA);
        const uint32_t o0 = sw128((uint32_t)(nsub * 128 + ks * 32 + khB));
        const uint32_t o1 = sw128((uint32_t)((16 + nsub) * 128 + ks * 32 + khB));
        LDSM4(wh0, bW + o0);  LDSM4(wh1, bW + o1);
        LDSM4(wl0, bW + 4096 + o0);  LDSM4(wl1, bW + 4096 + o1);
        mma16816(acc[0], ah, wh0[0], wh0[1]);
        mma16816(acc[0], al, wh0[0], wh0[1]);
        mma16816(acc[0], ah, wl0[0], wl0[1]);
        mma16816(acc[1], ah, wh0[2], wh0[3]);
        mma16816(acc[1], al, wh0[2], wh0[3]);
        mma16816(acc[1], ah, wl0[2], wl0[3]);
        mma16816(acc[2], ah, wh1[0], wh1[1]);
        mma16816(acc[2], al, wh1[0], wh1[1]);
        mma16816(acc[2], ah, wl1[0], wl1[1]);
        mma16816(acc[3], ah, wh1[2], wh1[3]);
        mma16816(acc[3], al, wh1[2], wh1[3]);
        mma16816(acc[3], ah, wl1[2], wl1[3]);
    }
    MBAR_ARRIVE(smem_u32(&sEmpty[s]));
    C.ci++; if (!(C.ci & (NSTG - 1))) C.cph ^= 1;
}

__device__ void gemm_pair(Cur& C, uint32_t smb, float acc[4][4], int nch, char* (*srcs)[3]) {
#pragma unroll
    for (int i = 0; i < 4; i++)
#pragma unroll
        for (int j = 0; j < 4; j++) acc[i][j] = 0.f;
    const int pre = nch < NSTG - 1 ? nch : NSTG - 1;
    for (int i = 0; i < pre; i++) produce(C, smb, srcs[i]);
    for (int i = 0; i < nch; i++) {
        if (i + pre < nch) produce(C, smb, srcs[i + pre]);
        consume(C, smb, acc);
    }
}

// ---------------- epilogue ---------------------------------------------------
__device__ void epilogue(float acc[4][4], float* D, int layer, float* cst,
                         char* hhi, char* hlo, float* hf, int n0) {
    const int tid = threadIdx.x, lane = tid & 31, w = tid >> 5;
    const int r0 = 16 * w + (lane >> 2), col = 2 * (lane & 3);
    __syncthreads();                                  // D free (prev reads done)
#pragma unroll
    for (int nt = 0; nt < 4; nt++) {
        *(float2*)&D[r0 * D_PITCH + nt * 8 + col]       = make_float2(acc[nt][0], acc[nt][1]);
        *(float2*)&D[(r0 + 8) * D_PITCH + nt * 8 + col] = make_float2(acc[nt][2], acc[nt][3]);
    }
    __syncthreads();
    const int u = tid & 7;
#pragma unroll
    for (int q = 0; q < 4; q++) {
        const int b = (tid >> 3) + 32 * q;
        const float4 g4 = *(const float4*)&D[b * D_PITCH + u * 4];
        const float iv = g4.x + sBias[layer * 32 + u * 4 + 0];
        const float fv = g4.y + sBias[layer * 32 + u * 4 + 1];
        const float gv = g4.z + sBias[layer * 32 + u * 4 + 2];
        const float ov = g4.w + sBias[layer * 32 + u * 4 + 3];
        const float cn = sigm(fv) * cst[q] + sigm(iv) * tanhf(gv);
        cst[q] = cn;
        const float h = sigm(ov) * tanhf(cn);
        const int n = n0 + u;
        const uint32_t sw = sw256((uint32_t)((n & 63) * 256 + b * 2)) + (n >> 6) * 16384;
        const __nv_bfloat16 hi = __float2bfloat16(h);
        *(__nv_bfloat16*)(hhi + sw) = hi;
        *(__nv_bfloat16*)(hlo + sw) = __float2bfloat16(h - __bfloat162float(hi));
        if (hf) hf[b * Hd + n] = h;
    }
}

// ---------------- output linear (K=1024 fp32) --------------------------------
__device__ void linear_out(const float* __restrict__ W, const float* __restrict__ bias, int c) {
    const int tid = threadIdx.x, d = tid >> 2, qt = tid & 3;
    const float* hb = gH2f + c * Hd + qt * 256;
    const float* wd = W + d * Hd + qt * 256;
    float s = 0.f;
#pragma unroll 8
    for (int k = 0; k < 256; k += 4) {
        const float4 hv = __ldcg((const float4*)(hb + k));
        const float4 wv = __ldg((const float4*)(wd + k));
        s += hv.x * wv.x + hv.y * wv.y + hv.z * wv.z + hv.w * wv.w;
    }
    s += __shfl_xor_sync(0xffffffffu, s, 1);
    s += __shfl_xor_sync(0xffffffffu, s, 2);
    if (qt == 0) {
        const float v = s + __ldg(bias + d);
        gOut[c * DIN + d] = v;
        const uint32_t sw = sw256((uint32_t)(d * 256 + c * 2));
        const __nv_bfloat16 hi = __float2bfloat16(v);
        *((__nv_bfloat16*)((char*)gOutT + sw)) = hi;
        *((__nv_bfloat16*)((char*)gOutT + 16384 + sw)) = __float2bfloat16(v - __bfloat162float(hi));
    }
}

// ---------------- precompute: repack into bulk-copyable layouts --------------
__device__ __forceinline__ void wsplit(float v, char* dsth, char* dstl, uint32_t off) {
    const __nv_bfloat16 h = __float2bfloat16(v);
    *(__nv_bfloat16*)(dsth + off) = h;
    *(__nv_bfloat16*)(dstl + off) = __float2bfloat16(v - __bfloat162float(h));
}
__device__ void packW(const float* __restrict__ W, int K, char* dst, int ncc, long t0, long nt) {
    const long tot = 128L * ncc * 2048;
    for (long i = t0; i < tot; i += nt) {
        const int c = (int)(i / (ncc * 2048));
        const int rem = (int)(i % (ncc * 2048));
        const int cc = rem >> 11, e = rem & 2047;
        const int np = e >> 6, k = e & 63;
        const float v = W[(long)((np & 3) * 1024 + c * 8 + (np >> 2)) * K + cc * 64 + k];
        const uint32_t sw = sw128((uint32_t)(np * 128 + k * 2));
        char* base = dst + ((long)(c * ncc + cc) * 2) * 4096;
        wsplit(v, base, base + 4096, sw);
    }
}
__global__ void precompute(
    const float* __restrict__ x,
    const float* __restrict__ Wih1, const float* __restrict__ Whh1,
    const float* __restrict__ bih1, const float* __restrict__ bhh1,
    const float* __restrict__ Wih2, const float* __restrict__ Whh2,
    const float* __restrict__ bih2, const float* __restrict__ bhh2)
{
    const long t0 = (long)blockIdx.x * blockDim.x + threadIdx.x;
    const long nt = (long)gridDim.x * blockDim.x;
    packW(Wih1, DIN, (char*)gPWih1, 1, t0, nt);
    packW(Whh1, Hd, (char*)gPWhh1, 16, t0, nt);
    packW(Wih2, Hd, (char*)gPWih2, 16, t0, nt);
    packW(Whh2, Hd, (char*)gPWhh2, 16, t0, nt);
    for (long i = t0; i < 128L * 8192; i += nt) {
        const int t = (int)(i >> 13), e = (int)(i & 8191);
        const int k = e >> 7, b = e & 127;
        const float v = x[(long)b * (TSEQ * DIN) + t * DIN + k];
        const uint32_t sw = sw256((uint32_t)(k * 256 + b * 2));
        char* base = (char*)gPX + (long)t * 32768;
        wsplit(v, base, base + 16384, sw);
    }
    for (long i = t0; i < 4096; i += nt) {
        gBias[0][i] = bih1[i] + bhh1[i];
        gBias[1][i] = bih2[i] + bhh2[i];
    }
}

// ---------------- persistent fused kernel ------------------------------------
__global__ void __launch_bounds__(NTHR, 1) lstm_hmma(
    const float* __restrict__ Wlin, const float* __restrict__ blin,
    const float* __restrict__ Whio, const float* __restrict__ bhio,
    const int* __restrict__ futp, float* __restrict__ out)
{
    extern __shared__ __align__(128) char dyn[];
    const uint32_t smb = smem_u32(dyn);
    float* D = (float*)(dyn + OFF_D);
    const int tid = threadIdx.x, c = blockIdx.x;
    const int n0 = c * 8;

    if (tid == 0) {
#pragma unroll
        for (int s = 0; s < NSTG; s++) {
            MBAR_INIT(smem_u32(&sFull[s]), 1);
            MBAR_INIT(smem_u32(&sEmpty[s]), NTHR);
        }
    }
    if (tid < 64) {
        const int l = tid >> 5, np = tid & 31;
        sBias[tid] = gBias[l][(np & 3) * 1024 + n0 + (np >> 2)];
    }
    // zero parity-0 h planes (this CTA's 8 k-rows, both planes, both layers)
    {
        char* bases[4] = { (char*)gH1T, (char*)gH1T + 262144,
                           (char*)gH2T, (char*)gH2T + 262144 };
        const uint32_t off = (uint32_t)(c >> 3) * 16384 + ((8 * c) & 63) * 256;
#pragma unroll
        for (int a = 0; a < 4; a++)
            *(uint64_t*)(bases[a] + off + tid * 8) = 0ULL;
    }
    const int fut = *futp;
    __syncthreads();
    grid_bar();

    Cur C; C.pi = 0; C.ci = 0; C.pph = 1; C.cph = 0;
    float acc[4][4], c1s[4], c2s[4];
#pragma unroll
    for (int q = 0; q < 4; q++) { c1s[q] = 0.f; c2s[q] = 0.f; }
    int p = 0;
    char* s1[17][3];
    char* s2[32][3];

    for (int t = 0; t < TSEQ + 0; t++) {
        // ---- layer 1: x_t @ Wih1^T + h1 @ Whh1^T
        char* h1p = (char*)gH1T + p * 524288;
        char* h1n = (char*)gH1T + (1 - p) * 524288;
        s1[0][0] = (char*)gPX + (long)t * 32768;
        s1[0][1] = s1[0][0] + 16384;
        s1[0][2] = (char*)gPWih1 + (long)c * 8192;
        for (int cc = 0; cc < 16; cc++) {
            s1[1 + cc][0] = h1p + cc * 16384;
            s1[1 + cc][1] = h1p + 262144 + cc * 16384;
            s1[1 + cc][2] = (char*)gPWhh1 + (long)(c * 16 + cc) * 8192;
        }
        gemm_pair(C, smb, acc, 17, s1);
        epilogue(acc, D, 0, c1s, h1n, h1n + 262144, nullptr, n0);
        grid_bar();
        // ---- layer 2: h1new @ Wih2^T + h2 @ Whh2^T
        char* h2p = (char*)gH2T + p * 524288;
        char* h2n = (char*)gH2T + (1 - p) * 524288;
        for (int cc = 0; cc < 16; cc++) {
            s2[cc][0] = h2p + cc * 16384;
            s2[cc][1] = h2p + 262144 + cc * 16384;
            s2[cc][2] = (char*)gPWhh2 + (long)(c * 16 + cc) * 8192;
            s2[16 + cc][0] = h1n + cc * 16384;
            s2[16 + cc][1] = h1n + 262144 + cc * 16384;
            s2[16 + cc][2] = (char*)gPWih2 + (long)(c * 16 + cc) * 8192;
        }
        gemm_pair(C, smb, acc, 32, s2);
        epilogue(acc, D, 1, c2s, h2n, h2n + 262144, gH2f, n0);
        grid_bar();
        p ^= 1;
    }

    linear_out(Wlin, blin, c);
    grid_bar();

    for (int f = 0; f < fut; f++) {
        char* h1p = (char*)gH1T + p * 524288;
        char* h1n = (char*)gH1T + (1 - p) * 524288;
        s1[0][0] = (char*)gOutT;
        s1[0][1] = (char*)gOutT + 16384;
        s1[0][2] = (char*)gPWih1 + (long)c * 8192;
        for (int cc = 0; cc < 16; cc++) {
            s1[1 + cc][0] = h1p + cc * 16384;
            s1[1 + cc][1] = h1p + 262144 + cc * 16384;
            s1[1 + cc][2] = (char*)gPWhh1 + (long)(c * 16 + cc) * 8192;
        }
        gemm_pair(C, smb, acc, 17, s1);
        epilogue(acc, D, 0, c1s, h1n, h1n + 262144, nullptr, n0);
        grid_bar();
        char* h2p = (char*)gH2T + p * 524288;
        char* h2n = (char*)gH2T + (1 - p) * 524288;
        for (int cc = 0; cc < 16; cc++) {
            s2[cc][0] = h2p + cc * 16384;
            s2[cc][1] = h2p + 262144 + cc * 16384;
            s2[cc][2] = (char*)gPWhh2 + (long)(c * 16 + cc) * 8192;
            s2[16 + cc][0] = h1n + cc * 16384;
            s2[16 + cc][1] = h1n + 262144 + cc * 16384;
            s2[16 + cc][2] = (char*)gPWih2 + (long)(c * 16 + cc) * 8192;
        }
        gemm_pair(C, smb, acc, 32, s2);
        epilogue(acc, D, 1, c2s, h2n, h2n + 262144, gH2f, n0);
        grid_bar();
        p ^= 1;
        linear_out(Whio, bhio, c);
        grid_bar();
    }

    for (int d = tid; d < DIN; d += NTHR)
        out[c * DIN + d] = gOut[c * DIN + d];
}

extern "C" void kernel_launch(void* const* d_in, const int* in_sizes, int n_in,
                              void* d_out, int out_size)
{
    const float* x    = (const float*)d_in[0];
    const float* Wih1 = (const float*)d_in[1];
    const float* Whh1 = (const float*)d_in[2];
    const float* bih1 = (const float*)d_in[3];
    const float* bhh1 = (const float*)d_in[4];
    const float* Wih2 = (const float*)d_in[5];
    const float* Whh2 = (const float*)d_in[6];
    const float* bih2 = (const float*)d_in[7];
    const float* bhh2 = (const float*)d_in[8];
    const float* Wlin = (const float*)d_in[9];
    const float* blin = (const float*)d_in[10];
    const float* Whio = (const float*)d_in[11];
    const float* bhio = (const float*)d_in[12];
    const int*   futp = (const int*)d_in[13];

    cudaFuncSetAttribute(lstm_hmma, cudaFuncAttributeMaxDynamicSharedMemorySize, DYN_SMEM);

    precompute<<<1024, 256>>>(x, Wih1, Whh1, bih1, bhh1, Wih2, Whh2, bih2, bhh2);
    lstm_hmma<<<GRID, NTHR, DYN_SMEM>>>(Wlin, blin, Whio, bhio, futp, (float*)d_out);
}

// round 7
// speedup vs baseline: 8.4225x; 1.3233x over previous
#include <cuda_runtime.h>
#include <cuda_bf16.h>
#include <cstdint>

#define Hd    1024
#define TSEQ  128
#define DIN   64
#define GRID  128
#define NTHR  256

#define NSTG      5
#define SLOT_SZ   40960                    // Ah 16K | Al 16K | Wh 4K | Wl 4K
#define DYN_SMEM  (NSTG * SLOT_SZ)        // 204800

#define BT(k) (128u * (unsigned)(k))

// ---------------- device globals (packed layouts; no allocation) ------------
__device__ __align__(1024) __nv_bfloat16 gPWih1[128][2][2048];       // [c][pl][32*64]
__device__ __align__(1024) __nv_bfloat16 gPWhh1[128][16][2][2048];
__device__ __align__(1024) __nv_bfloat16 gPWih2[128][16][2][2048];
__device__ __align__(1024) __nv_bfloat16 gPWhh2[128][16][2][2048];
__device__ __align__(1024) __nv_bfloat16 gPX[TSEQ][2][8192];         // [t][pl][64k*128b]
__device__ __align__(1024) __nv_bfloat16 gH1T[2][2][131072];         // [par][pl][1024k*128b]
__device__ __align__(1024) __nv_bfloat16 gH2T[2][2][131072];
__device__ __align__(1024) __nv_bfloat16 gOutT[2][8192];             // [pl][64k*128b]
__device__ float gH2f[128 * Hd];
__device__ float gOut[128 * DIN];
__device__ float gBias[2][4096];
__device__ unsigned g_bar_cnt;
__device__ volatile unsigned g_bar_gen;
__device__ unsigned g_ticket;              // monotonic split-barrier counter (reset at launch entry)

// ---------------- PTX helpers ------------------------------------------------
__device__ __forceinline__ uint32_t smem_u32(const void* p) {
    uint32_t a;
    asm("{ .reg .u64 t; cvta.to.shared.u64 t, %1; cvt.u32.u64 %0, t; }" : "=r"(a) : "l"(p));
    return a;
}
#define MBAR_INIT(a, c) \
    asm volatile("mbarrier.init.shared.b64 [%0], %1;" :: "r"(a), "r"((uint32_t)(c)) : "memory")
#define MBAR_ARRIVE(a) \
    asm volatile("mbarrier.arrive.shared.b64 _, [%0];" :: "r"(a) : "memory")
#define MBAR_EXPECT_TX(a, n) \
    asm volatile("mbarrier.arrive.expect_tx.shared.b64 _, [%0], %1;" :: "r"(a), "r"((uint32_t)(n)) : "memory")
#define MBAR_WAIT(a, ph) do { \
    uint32_t _m = (a), _p = (uint32_t)(ph), _d; \
    asm volatile("{\n\t.reg .pred p;\n\t" \
        "mbarrier.try_wait.parity.acquire.cta.shared::cta.b64 p, [%1], %2;\n\t" \
        "selp.b32 %0, 1, 0, p;\n\t}" : "=r"(_d) : "r"(_m), "r"(_p) : "memory"); \
    if (!_d) { \
        asm volatile("{\n\t.reg .pred P1;\n\t" \
            "WL_%=:\n\t" \
            "mbarrier.try_wait.parity.acquire.cta.shared::cta.b64 P1, [%0], %1, 0x989680;\n\t" \
            "@P1 bra.uni WD_%=;\n\tbra.uni WL_%=;\n\tWD_%=:\n\t}" \
            :: "r"(_m), "r"(_p) : "memory"); \
    } } while (0)
#define BULK_G2S(dst, src, sz, mb) \
    asm volatile("cp.async.bulk.shared::cta.global.mbarrier::complete_tx::bytes [%0], [%1], %2, [%3];" \
                 :: "r"(dst), "l"(src), "r"((uint32_t)(sz)), "r"(mb) : "memory")
#define LDSM4(r, a) \
    asm volatile("ldmatrix.sync.aligned.m8n8.x4.shared.b16 {%0,%1,%2,%3},[%4];" \
        : "=r"((r)[0]), "=r"((r)[1]), "=r"((r)[2]), "=r"((r)[3]) : "r"(a))
#define LDSM4T(r, a) \
    asm volatile("ldmatrix.sync.aligned.m8n8.x4.trans.shared.b16 {%0,%1,%2,%3},[%4];" \
        : "=r"((r)[0]), "=r"((r)[1]), "=r"((r)[2]), "=r"((r)[3]) : "r"(a))

__device__ __forceinline__ void mma16816(float* c, const uint32_t* a, uint32_t b0, uint32_t b1) {
    asm volatile("mma.sync.aligned.m16n8k16.row.col.f32.bf16.bf16.f32 "
                 "{%0,%1,%2,%3},{%4,%5,%6,%7},{%8,%9},{%0,%1,%2,%3};"
                 : "+f"(c[0]), "+f"(c[1]), "+f"(c[2]), "+f"(c[3])
                 : "r"(a[0]), "r"(a[1]), "r"(a[2]), "r"(a[3]), "r"(b0), "r"(b1));
}
__device__ __forceinline__ uint32_t sw128(uint32_t o) { return o ^ ((o >> 3) & 0x70); }
__device__ __forceinline__ uint32_t sw256(uint32_t o) { return o ^ ((o >> 4) & 0x70); }
__device__ __forceinline__ float sigm(float v) { return 1.0f / (1.0f + __expf(-v)); }

// ---------------- launch-entry classic barrier (also resets ticket) ----------
__device__ __forceinline__ void init_bar() {
    __syncthreads();
    if (threadIdx.x == 0) {
        unsigned gen = g_bar_gen;
        __threadfence();
        unsigned t = atomicAdd(&g_bar_cnt, 1u);
        if (t == GRID - 1) {
            g_ticket = 0;                          // reset split-barrier counter
            atomicExch(&g_bar_cnt, 0u);
            __threadfence();
            g_bar_gen = gen + 1;
        } else {
            while (g_bar_gen == gen) { __nanosleep(64); }
        }
        __threadfence();
    }
    __syncthreads();
}

// ---------------- split barrier primitives -----------------------------------
__device__ __forceinline__ void bar_arrive() {       // after all-thread global writes
    __threadfence();
    __syncthreads();
    if (threadIdx.x == 0) atomicAdd(&g_ticket, 1u);
}
__device__ __forceinline__ void wait_all(unsigned target) {
    if (threadIdx.x == 0) {
        while (*(volatile unsigned*)&g_ticket < target) __nanosleep(32);
    }
    __syncthreads();
    __threadfence();
}

// ---------------- pipeline ---------------------------------------------------
struct Cur { unsigned pi, ci; };
__shared__ __align__(8) uint64_t sFull[NSTG], sEmpty[NSTG];
__shared__ float sBias[64];

__device__ __forceinline__ void produce(Cur& C, uint32_t smb, char* const* src, unsigned dep) {
    const unsigned s = C.pi % NSTG;
    if (threadIdx.x == 0) {
        if (dep) {
            while (*(volatile unsigned*)&g_ticket < dep) __nanosleep(32);
            __threadfence();
        }
        MBAR_WAIT(smem_u32(&sEmpty[s]), 1 ^ ((C.pi / NSTG) & 1));
        const uint32_t mf = smem_u32(&sFull[s]);
        MBAR_EXPECT_TX(mf, SLOT_SZ);
        const uint32_t d = smb + s * SLOT_SZ;
        BULK_G2S(d,          src[0], 16384, mf);
        BULK_G2S(d + 16384,  src[1], 16384, mf);
        BULK_G2S(d + 32768,  src[2], 8192,  mf);
    }
    C.pi++;
}

__device__ __forceinline__ void consume(Cur& C, uint32_t smb, float acc[4][4]) {
    const unsigned s = C.ci % NSTG;
    MBAR_WAIT(smem_u32(&sFull[s]), (C.ci / NSTG) & 1);
    const uint32_t bA = smb + s * SLOT_SZ;
    const uint32_t bW = bA + 32768;
    const int lane = threadIdx.x & 31, w = threadIdx.x >> 5;
    const int kpart = ((lane >> 4) & 1) * 8 + (lane & 7);
    const int bsegA = (w << 5) + ((lane >> 3) & 1) * 16;
    const int nsub  = ((lane >> 4) & 1) * 8 + (lane & 7);
    const int khB   = ((lane >> 3) & 1) * 16;
#pragma unroll
    for (int ks = 0; ks < 4; ks++) {
        uint32_t ah[4], al[4], wh0[4], wh1[4], wl0[4], wl1[4];
        const uint32_t oA = sw256((uint32_t)((ks * 16 + kpart) * 256 + bsegA));
        LDSM4T(ah, bA + oA);
        LDSM4T(al, bA + 16384 + oA);
        const uint32_t o0 = sw128((uint32_t)(nsub * 128 + ks * 32 + khB));
        const uint32_t o1 = sw128((uint32_t)((16 + nsub) * 128 + ks * 32 + khB));
        LDSM4(wh0, bW + o0);  LDSM4(wh1, bW + o1);
        LDSM4(wl0, bW + 4096 + o0);  LDSM4(wl1, bW + 4096 + o1);
        mma16816(acc[0], ah, wh0[0], wh0[1]);
        mma16816(acc[0], al, wh0[0], wh0[1]);
        mma16816(acc[0], ah, wl0[0], wl0[1]);
        mma16816(acc[1], ah, wh0[2], wh0[3]);
        mma16816(acc[1], al, wh0[2], wh0[3]);
        mma16816(acc[1], ah, wl0[2], wl0[3]);
        mma16816(acc[2], ah, wh1[0], wh1[1]);
        mma16816(acc[2], al, wh1[0], wh1[1]);
        mma16816(acc[2], ah, wl1[0], wl1[1]);
        mma16816(acc[3], ah, wh1[2], wh1[3]);
        mma16816(acc[3], al, wh1[2], wh1[3]);
        mma16816(acc[3], ah, wl1[2], wl1[3]);
    }
    if ((threadIdx.x & 31) == 0) MBAR_ARRIVE(smem_u32(&sEmpty[s]));
    C.ci++;
}

// ---------------- shuffle-only epilogue --------------------------------------
// Each lane pair (lane, lane^1) exchanges 2 floats per n-tile so every thread
// assembles all 4 gates for 4 (batch,unit) pairs. No smem, no syncthreads.
__device__ __forceinline__ void epilogue(float acc[4][4], const float* sB, float* cst,
                                         char* hhi, char* hlo, float* hf, int n0) {
    const int lane = threadIdx.x & 31, w = threadIdx.x >> 5;
    const int odd = lane & 1;
    const int b = 16 * w + (lane >> 2) + odd * 8;
    const int ubase = (lane & 3) >> 1;
#pragma unroll
    for (int nt = 0; nt < 4; nt++) {
        const float s0 = odd ? acc[nt][0] : acc[nt][2];
        const float s1 = odd ? acc[nt][1] : acc[nt][3];
        const float r0 = __shfl_xor_sync(0xffffffffu, s0, 1);
        const float r1 = __shfl_xor_sync(0xffffffffu, s1, 1);
        const float gi = odd ? r0 : acc[nt][0];
        const float gf = odd ? r1 : acc[nt][1];
        const float gg = odd ? acc[nt][2] : r0;
        const float go = odd ? acc[nt][3] : r1;
        const int u = 2 * nt + ubase;
        const float iv = gi + sB[u * 4 + 0];
        const float fv = gf + sB[u * 4 + 1];
        const float gv = gg + sB[u * 4 + 2];
        const float ov = go + sB[u * 4 + 3];
        const float cn = sigm(fv) * cst[nt] + sigm(iv) * tanhf(gv);
        cst[nt] = cn;
        const float h = sigm(ov) * tanhf(cn);
        const int n = n0 + u;
        const uint32_t sw = sw256((uint32_t)((n & 63) * 256 + b * 2)) + (n >> 6) * 16384;
        const __nv_bfloat16 hi = __float2bfloat16(h);
        *(__nv_bfloat16*)(hhi + sw) = hi;
        *(__nv_bfloat16*)(hlo + sw) = __float2bfloat16(h - __bfloat162float(hi));
        if (hf) hf[b * Hd + n] = h;
    }
}

// ---------------- output linear (K=1024 fp32) --------------------------------
__device__ void linear_out(const float* __restrict__ W, const float* __restrict__ bias, int c) {
    const int tid = threadIdx.x, d = tid >> 2, qt = tid & 3;
    const float* hb = gH2f + c * Hd + qt * 256;
    const float* wd = W + d * Hd + qt * 256;
    float s = 0.f;
#pragma unroll 8
    for (int k = 0; k < 256; k += 4) {
        const float4 hv = __ldcg((const float4*)(hb + k));
        const float4 wv = __ldg((const float4*)(wd + k));
        s += hv.x * wv.x + hv.y * wv.y + hv.z * wv.z + hv.w * wv.w;
    }
    s += __shfl_xor_sync(0xffffffffu, s, 1);
    s += __shfl_xor_sync(0xffffffffu, s, 2);
    if (qt == 0) {
        const float v = s + __ldg(bias + d);
        gOut[c * DIN + d] = v;
        const uint32_t sw = sw256((uint32_t)(d * 256 + c * 2));
        const __nv_bfloat16 hi = __float2bfloat16(v);
        *((__nv_bfloat16*)((char*)gOutT + sw)) = hi;
        *((__nv_bfloat16*)((char*)gOutT + 16384 + sw)) = __float2bfloat16(v - __bfloat162float(hi));
    }
}

// ---------------- chunk source resolution ------------------------------------
__device__ __forceinline__ void chunk_src(int j, char* x0, char* x1,
                                          char* h1p, char* h2p, char* h1n,
                                          const char* w1, const char* whh1,
                                          const char* whh2, const char* wih2,
                                          char* src[3]) {
    if (j == 0) { src[0] = x0; src[1] = x1; src[2] = (char*)w1; }
    else if (j < 17) { const int cc = j - 1;
        src[0] = h1p + cc * 16384; src[1] = h1p + 262144 + cc * 16384;
        src[2] = (char*)whh1 + cc * 8192; }
    else if (j < 33) { const int cc = j - 17;
        src[0] = h2p + cc * 16384; src[1] = h2p + 262144 + cc * 16384;
        src[2] = (char*)whh2 + cc * 8192; }
    else { const int cc = j - 33;
        src[0] = h1n + cc * 16384; src[1] = h1n + 262144 + cc * 16384;
        src[2] = (char*)wih2 + cc * 8192; }
}

// ---------------- one full LSTM step (49 chunks, 2 epilogues, 2 arrives) -----
__device__ void run_step(Cur& C, uint32_t smb, int n0,
                         char* x0, char* x1, char* h1p, char* h2p, char* h1n, char* h2n,
                         const char* w1, const char* whh1, const char* whh2, const char* wih2,
                         unsigned d0, unsigned d1, unsigned d17, unsigned d33,
                         float* c1s, float* c2s) {
    float acc[4][4];
#pragma unroll
    for (int i = 0; i < 4; i++)
#pragma unroll
        for (int j = 0; j < 4; j++) acc[i][j] = 0.f;
    char* src[3];
#pragma unroll
    for (int j = 0; j < 4; j++) {                 // prologue: fill 4 slots
        chunk_src(j, x0, x1, h1p, h2p, h1n, w1, whh1, whh2, wih2, src);
        produce(C, smb, src, j == 0 ? d0 : (j == 1 ? d1 : 0));
    }
    for (int i = 0; i < 49; i++) {
        const int j = i + 4;
        if (j < 49) {
            chunk_src(j, x0, x1, h1p, h2p, h1n, w1, whh1, whh2, wih2, src);
            produce(C, smb, src, j == 17 ? d17 : (j == 33 ? d33 : 0));
        }
        consume(C, smb, acc);
        if (i == 16) {
            epilogue(acc, sBias, c1s, h1n, h1n + 262144, nullptr, n0);
            bar_arrive();                         // B1[t]
#pragma unroll
            for (int a = 0; a < 4; a++)
#pragma unroll
                for (int bq = 0; bq < 4; bq++) acc[a][bq] = 0.f;
        }
    }
    epilogue(acc, sBias + 32, c2s, h2n, h2n + 262144, gH2f, n0);
    bar_arrive();                                 // B2[t]
}

// ---------------- precompute: repack into bulk-copyable layouts --------------
__device__ __forceinline__ void wsplit(float v, char* dsth, char* dstl, uint32_t off) {
    const __nv_bfloat16 h = __float2bfloat16(v);
    *(__nv_bfloat16*)(dsth + off) = h;
    *(__nv_bfloat16*)(dstl + off) = __float2bfloat16(v - __bfloat162float(h));
}
__device__ void packW(const float* __restrict__ W, int K, char* dst, int ncc, long t0, long nt) {
    const long tot = 128L * ncc * 2048;
    for (long i = t0; i < tot; i += nt) {
        const int c = (int)(i / (ncc * 2048));
        const int rem = (int)(i % (ncc * 2048));
        const int cc = rem >> 11, e = rem & 2047;
        const int np = e >> 6, k = e & 63;
        const float v = W[(long)((np & 3) * 1024 + c * 8 + (np >> 2)) * K + cc * 64 + k];
        const uint32_t sw = sw128((uint32_t)(np * 128 + k * 2));
        char* base = dst + ((long)(c * ncc + cc) * 2) * 4096;
        wsplit(v, base, base + 4096, sw);
    }
}
__global__ void precompute(
    const float* __restrict__ x,
    const float* __restrict__ Wih1, const float* __restrict__ Whh1,
    const float* __restrict__ bih1, const float* __restrict__ bhh1,
    const float* __restrict__ Wih2, const float* __restrict__ Whh2,
    const float* __restrict__ bih2, const float* __restrict__ bhh2)
{
    const long t0 = (long)blockIdx.x * blockDim.x + threadIdx.x;
    const long nt = (long)gridDim.x * blockDim.x;
    packW(Wih1, DIN, (char*)gPWih1, 1, t0, nt);
    packW(Whh1, Hd, (char*)gPWhh1, 16, t0, nt);
    packW(Wih2, Hd, (char*)gPWih2, 16, t0, nt);
    packW(Whh2, Hd, (char*)gPWhh2, 16, t0, nt);
    for (long i = t0; i < 128L * 8192; i += nt) {
        const int t = (int)(i >> 13), e = (int)(i & 8191);
        const int k = e >> 7, b = e & 127;
        const float v = x[(long)b * (TSEQ * DIN) + t * DIN + k];
        const uint32_t sw = sw256((uint32_t)(k * 256 + b * 2));
        char* base = (char*)gPX + (long)t * 32768;
        wsplit(v, base, base + 16384, sw);
    }
    for (long i = t0; i < 4096; i += nt) {
        gBias[0][i] = bih1[i] + bhh1[i];
        gBias[1][i] = bih2[i] + bhh2[i];
    }
}

// ---------------- persistent fused kernel ------------------------------------
__global__ void __launch_bounds__(NTHR, 1) lstm_hmma(
    const float* __restrict__ Wlin, const float* __restrict__ blin,
    const float* __restrict__ Whio, const float* __restrict__ bhio,
    const int* __restrict__ futp, float* __restrict__ out)
{
    extern __shared__ __align__(128) char dyn[];
    const uint32_t smb = smem_u32(dyn);
    const int tid = threadIdx.x, c = blockIdx.x;
    const int n0 = c * 8;

    if (tid == 0) {
#pragma unroll
        for (int s = 0; s < NSTG; s++) {
            MBAR_INIT(smem_u32(&sFull[s]), 1);
            MBAR_INIT(smem_u32(&sEmpty[s]), 8);   // one arrival per warp
        }
    }
    if (tid < 64) {
        const int l = tid >> 5, np = tid & 31;
        sBias[tid] = gBias[l][(np & 3) * 1024 + n0 + (np >> 2)];
    }
    {   // zero parity-0 h planes (this CTA's 8 k-rows, both planes, both layers)
        char* bases[4] = { (char*)gH1T, (char*)gH1T + 262144,
                           (char*)gH2T, (char*)gH2T + 262144 };
        const uint32_t off = (uint32_t)(c >> 3) * 16384 + ((8 * c) & 63) * 256;
#pragma unroll
        for (int a = 0; a < 4; a++)
            *(uint64_t*)(bases[a] + off + tid * 8) = 0ULL;
    }
    const int fut = *futp;
    __syncthreads();
    init_bar();                                   // also resets g_ticket

    Cur C; C.pi = 0; C.ci = 0;
    float c1s[4], c2s[4];
#pragma unroll
    for (int q = 0; q < 4; q++) { c1s[q] = 0.f; c2s[q] = 0.f; }
    int p = 0;

    const char* whh1b = (const char*)gPWhh1 + (long)c * 16 * 8192;
    const char* whh2b = (const char*)gPWhh2 + (long)c * 16 * 8192;
    const char* wih2b = (const char*)gPWih2 + (long)c * 16 * 8192;
    const char* w1b   = (const char*)gPWih1 + (long)c * 8192;

    for (int t = 0; t < TSEQ; t++) {
        char* h1p = (char*)gH1T + p * 524288;
        char* h1n = (char*)gH1T + (1 - p) * 524288;
        char* h2p = (char*)gH2T + p * 524288;
        char* h2n = (char*)gH2T + (1 - p) * 524288;
        run_step(C, smb, n0,
                 (char*)gPX + (long)t * 32768, (char*)gPX + (long)t * 32768 + 16384,
                 h1p, h2p, h1n, h2n, w1b, whh1b, whh2b, wih2b,
                 0u, t ? BT(2 * t - 1) : 0u, t ? BT(2 * t) : 0u, BT(2 * t + 1),
                 c1s, c2s);
        p ^= 1;
    }

    wait_all(BT(2 * TSEQ));                       // B2[127]
    linear_out(Wlin, blin, c);
    bar_arrive();                                 // Lin0 = barrier 257

    for (int f = 0; f < fut; f++) {
        char* h1p = (char*)gH1T + p * 524288;
        char* h1n = (char*)gH1T + (1 - p) * 524288;
        char* h2p = (char*)gH2T + p * 524288;
        char* h2n = (char*)gH2T + (1 - p) * 524288;
        run_step(C, smb, n0,
                 (char*)gOutT, (char*)gOutT + 16384,
                 h1p, h2p, h1n, h2n, w1b, whh1b, whh2b, wih2b,
                 BT(257 + 3 * f), BT(255 + 3 * f), BT(256 + 3 * f), BT(258 + 3 * f),
                 c1s, c2s);
        p ^= 1;
        wait_all(BT(259 + 3 * f));                // B2 of this future step
        linear_out(Whio, bhio, c);
        bar_arrive();                             // Lin_{f+1}
    }

    __syncthreads();
    for (int d = tid; d < DIN; d += NTHR)
        out[c * DIN + d] = gOut[c * DIN + d];
}

extern "C" void kernel_launch(void* const* d_in, const int* in_sizes, int n_in,
                              void* d_out, int out_size)
{
    const float* x    = (const float*)d_in[0];
    const float* Wih1 = (const float*)d_in[1];
    const float* Whh1 = (const float*)d_in[2];
    const float* bih1 = (const float*)d_in[3];
    const float* bhh1 = (const float*)d_in[4];
    const float* Wih2 = (const float*)d_in[5];
    const float* Whh2 = (const float*)d_in[6];
    const float* bih2 = (const float*)d_in[7];
    const float* bhh2 = (const float*)d_in[8];
    const float* Wlin = (const float*)d_in[9];
    const float* blin = (const float*)d_in[10];
    const float* Whio = (const float*)d_in[11];
    const float* bhio = (const float*)d_in[12];
    const int*   futp = (const int*)d_in[13];

    cudaFuncSetAttribute(lstm_hmma, cudaFuncAttributeMaxDynamicSharedMemorySize, DYN_SMEM);

    precompute<<<1024, 256>>>(x, Wih1, Whh1, bih1, bhh1, Wih2, Whh2, bih2, bhh2);
    lstm_hmma<<<GRID, NTHR, DYN_SMEM>>>(Wlin, blin, Whio, bhio, futp, (float*)d_out);
}